// round 9
// baseline (speedup 1.0000x reference)
#include <cuda_runtime.h>
#include <cuda_bf16.h>
#include <math.h>

#define NN 50000
#define EE 600000
#define DD 128
#define NF (NN*DD)
#define NBLK 196   // ceil(NN/256)

// ---------------------------------------------------------------------------
// bf16 helpers
__device__ __forceinline__ unsigned packbf(float even, float odd) {
    unsigned d;
    asm("cvt.rn.bf16x2.f32 %0, %1, %2;" : "=r"(d) : "f"(odd), "f"(even));
    return d;
}
__device__ __forceinline__ float bfres(float v) {
    return v - __bfloat162float(__float2bfloat16(v));
}
__device__ __forceinline__ void mma_bf16(
    float& d0, float& d1, float& d2, float& d3,
    unsigned a0, unsigned a1, unsigned a2, unsigned a3,
    unsigned b0, unsigned b1) {
    asm volatile(
        "mma.sync.aligned.m16n8k16.row.col.f32.bf16.bf16.f32 "
        "{%0,%1,%2,%3},{%4,%5,%6,%7},{%8,%9},{%0,%1,%2,%3};"
        : "+f"(d0), "+f"(d1), "+f"(d2), "+f"(d3)
        : "r"(a0), "r"(a1), "r"(a2), "r"(a3), "r"(b0), "r"(b1));
}

// ---------------------------------------------------------------------------
// float scratch: HB,HA,H2A,H2B,HMLP + RS + STATS + BN + WT
#define OFF_HB    0ULL
#define OFF_HA    (1ULL*NF)
#define OFF_H2A   (2ULL*NF)
#define OFF_H2B   (3ULL*NF)
#define OFF_HMLP  (4ULL*NF)
#define OFF_RS    (5ULL*NF)
#define OFF_STATS (5ULL*NF + 4ULL*NN)
#define OFF_BN    (OFF_STATS + 256ULL)
#define OFF_WT    (OFF_BN + 256ULL)
#define SCRATCH_FLOATS (OFF_WT + 196608ULL)

__device__ __align__(256) float g_s[SCRATCH_FLOATS];

#define IOFF_EIDX0 0
#define IOFF_EIDX1 (EE)
#define IOFF_OD0   (2*EE)
#define IOFF_CNT0  (2*EE + NN)
#define IOFF_OD1   (2*EE + 2*NN)
#define IOFF_CNT1  (2*EE + 3*NN)
#define IOFF_RP0   (2*EE + 4*NN)
#define IOFF_RP1   (2*EE + 5*NN + 1)
#define IOFF_CUR0  (2*EE + 6*NN + 2)
#define IOFF_CUR1  (2*EE + 7*NN + 2)
#define IOFF_BSUM  (2*EE + 8*NN + 2)
#define IOFF_PFX   (IOFF_BSUM + 2*NBLK)
#define IOFF_SYNC  (IOFF_PFX + 2*NBLK)
#define SCRATCH_INTS (IOFF_SYNC + 2)

__device__ __align__(256) int g_i[SCRATCH_INTS];

// ---------------------------------------------------------------------------
__global__ void k_zero2(int* __restrict__ deg, float* __restrict__ stats,
                        int* __restrict__ syn) {
    int i = blockIdx.x * 256 + threadIdx.x;
    if (i < NN) ((int4*)deg)[i] = make_int4(0, 0, 0, 0);   // 4*NN ints
    if (i < 64) ((float4*)stats)[i] = make_float4(0.f, 0.f, 0.f, 0.f);
    if (i == 0) { syn[0] = 0; syn[1] = 0; }
}

__global__ void k_hist(const int* __restrict__ s0, const int* __restrict__ d0,
                       const int* __restrict__ s1, const int* __restrict__ d1,
                       int* __restrict__ od0, int* __restrict__ cnt0,
                       int* __restrict__ od1, int* __restrict__ cnt1) {
    int i = blockIdx.x * blockDim.x + threadIdx.x;
    if (i < EE) {
        atomicAdd(&od0[s0[i]], 1);
        atomicAdd(&cnt0[d0[i]], 1);
        atomicAdd(&od1[s1[i]], 1);
        atomicAdd(&cnt1[d1[i]], 1);
    }
}

// fused scan (verified in R7): block sums -> last block scans -> rowptr/cursor/rs
__global__ void __launch_bounds__(256) k_scan_fused(
    const int* __restrict__ c0, const int* __restrict__ c1,
    const int* __restrict__ od0, const int* __restrict__ od1,
    int* __restrict__ bsum, int* __restrict__ pfx, int* __restrict__ syn,
    int* __restrict__ rp0, int* __restrict__ rp1,
    int* __restrict__ cur0, int* __restrict__ cur1,
    float* __restrict__ rs) {
    __shared__ int sp[256];
    __shared__ int sp2[512];
    __shared__ int islast;
    int t = threadIdx.x;
    int y = blockIdx.y;
    const int* cnt = y ? c1 : c0;
    const int* od  = y ? od1 : od0;
    int* rp  = y ? rp1 : rp0;
    int* cur = y ? cur1 : cur0;
    int i = blockIdx.x * 256 + t;
    int v = (i < NN) ? cnt[i] : 0;

    sp[t] = v;
    __syncthreads();
    for (int off = 128; off; off >>= 1) {
        if (t < off) sp[t] += sp[t + off];
        __syncthreads();
    }
    if (t == 0) {
        bsum[y * NBLK + blockIdx.x] = sp[0];
        __threadfence();
        int old = atomicAdd(&syn[0], 1);
        islast = (old == 2 * NBLK - 1);
    }
    __syncthreads();

    if (islast) {
        for (int j = t; j < 2 * NBLK; j += 256) sp2[j] = ((volatile int*)bsum)[j];
        __syncthreads();
        for (int rel = 0; rel < 2; rel++) {
            int* a = sp2 + rel * NBLK;
            int mine = (t < NBLK) ? a[t] : 0;
            sp[t] = mine;
            __syncthreads();
            for (int off = 1; off < 256; off <<= 1) {
                int u = (t >= off) ? sp[t - off] : 0;
                __syncthreads();
                sp[t] += u;
                __syncthreads();
            }
            if (t < NBLK) pfx[rel * NBLK + t] = sp[t] - mine;
            __syncthreads();
        }
        if (t == 0) {
            __threadfence();
            atomicExch(&syn[1], 1);
        }
    }
    if (t == 0) {
        while (((volatile int*)syn)[1] == 0) __nanosleep(64);
    }
    __syncthreads();

    sp[t] = v;
    __syncthreads();
    for (int off = 1; off < 256; off <<= 1) {
        int u = (t >= off) ? sp[t - off] : 0;
        __syncthreads();
        sp[t] += u;
        __syncthreads();
    }
    if (i < NN) {
        int ex = sp[t] - v + ((volatile int*)pfx)[y * NBLK + blockIdx.x];
        rp[i] = ex;
        cur[i] = ex;
        rs[(2 * y + 0) * NN + i] = rsqrtf((float)max(od[i], 1));
        rs[(2 * y + 1) * NN + i] = rsqrtf((float)max(v, 1));
    }
    if (i == NN - 1) rp[NN] = EE;
}

__global__ void k_fill(const int* __restrict__ s0, const int* __restrict__ d0,
                       const int* __restrict__ s1, const int* __restrict__ d1,
                       int* __restrict__ cur0, int* __restrict__ eidx0,
                       int* __restrict__ cur1, int* __restrict__ eidx1) {
    int i = blockIdx.x * blockDim.x + threadIdx.x;
    if (i < EE) {
        int p0 = atomicAdd(&cur0[d0[i]], 1);
        eidx0[p0] = s0[i];
        int p1 = atomicAdd(&cur1[d1[i]], 1);
        eidx1[p1] = s1[i];
    }
}

// ---------------------------------------------------------------------------
// weight prep (unchanged)
__global__ void k_wprep(const float* __restrict__ W1r0, const float* __restrict__ W1r1,
                        const float* __restrict__ W2r0, const float* __restrict__ W2r1,
                        const float* __restrict__ Wm1, unsigned* __restrict__ WT) {
    int idx = blockIdx.x * 256 + threadIdx.x;
    if (idx < 32768) {
        int mat = idx >> 13, r = idx & 8191;
        int n = r >> 6, ku = r & 63;
        int k = 2 * ku;
        const float* Wsrc = (mat == 0) ? W1r0 : (mat == 1) ? W1r1 :
                            (mat == 2) ? W2r0 : W2r1;
        float v0 = __ldg(Wsrc + k * 128 + n);
        float v1 = __ldg(Wsrc + (k + 1) * 128 + n);
        WT[mat * 16384 + n * 64 + ku]        = packbf(v0, v1);
        WT[mat * 16384 + 8192 + n * 64 + ku] = packbf(bfres(v0), bfres(v1));
    } else if (idx < 49152) {
        int r = idx - 32768;
        int n = r >> 7, ku = r & 127;
        int k = 2 * ku;
        float v0 = __ldg(Wm1 + k * 128 + n);
        float v1 = __ldg(Wm1 + (k + 1) * 128 + n);
        WT[65536 + n * 128 + ku]         = packbf(v0, v1);
        WT[65536 + 16384 + n * 128 + ku] = packbf(bfres(v0), bfres(v1));
    }
}

// ---------------------------------------------------------------------------
// FUSED conv: gather (CSR, per-edge scale optional) -> row scale -> bf16x3 MMA
// 64-row tiles, both relations per launch (grid.y). No AGG round-trip.
#define U_AHI 0
#define U_ALO 4352
#define U_WHI 8704
#define U_WLO 17408
#define SMEM_G ((size_t)26112 * 4)   // 104448 B

__global__ void __launch_bounds__(256, 2) k_conv_fused(
    const float* __restrict__ X0, const int* __restrict__ e0,
    const int* __restrict__ rpA, const float* __restrict__ rse0,
    const float* __restrict__ rsr0, const unsigned* __restrict__ Wp0,
    const float* __restrict__ bp0, float* __restrict__ out0,
    const float* __restrict__ rso0,
    const float* __restrict__ X1, const int* __restrict__ e1,
    const int* __restrict__ rpB, const float* __restrict__ rse1,
    const float* __restrict__ rsr1, const unsigned* __restrict__ Wp1,
    const float* __restrict__ bp1, float* __restrict__ out1,
    const float* __restrict__ rso1,
    int useRs, int doRelu) {
    extern __shared__ unsigned smu[];
    unsigned* sAhi = smu + U_AHI;
    unsigned* sAlo = smu + U_ALO;
    unsigned* sWhi = smu + U_WHI;
    unsigned* sWlo = smu + U_WLO;

    const float* X = blockIdx.y ? X1 : X0;
    const int* eidx = blockIdx.y ? e1 : e0;
    const int* rowptr = blockIdx.y ? rpB : rpA;
    const float* rs_edge = blockIdx.y ? rse1 : rse0;
    const float* rs_row = blockIdx.y ? rsr1 : rsr0;
    const unsigned* Wp = blockIdx.y ? Wp1 : Wp0;
    const float* bp = blockIdx.y ? bp1 : bp0;
    float* out = blockIdx.y ? out1 : out0;
    const float* rso = blockIdx.y ? rso1 : rso0;

    int tid = threadIdx.x;
    int r0 = blockIdx.x * 64;
    int lane = tid & 31, w = tid >> 5;

    // stage W planes
    for (int i = tid; i < 4096; i += 256) {
        int n = i >> 5, q = i & 31;
        ((uint2*)(sWhi + n * 68))[q] = __ldg((const uint2*)(Wp + n * 64) + q);
        ((uint2*)(sWlo + n * 68))[q] = __ldg((const uint2*)(Wp + 8192 + n * 64) + q);
    }

    // gather phase: warp w handles rows w*8 .. w*8+7; lane owns float4 #lane
    for (int rr = 0; rr < 8; rr++) {
        int row = w * 8 + rr;
        int gr = r0 + row;
        float4 acc = make_float4(0.f, 0.f, 0.f, 0.f);
        if (gr < NN) {
            int beg = __ldg(rowptr + gr), end = __ldg(rowptr + gr + 1);
            int e = beg;
            if (useRs) {
                for (; e + 3 < end; e += 4) {
                    int sa = __ldg(eidx + e),     sb = __ldg(eidx + e + 1);
                    int sc = __ldg(eidx + e + 2), sd = __ldg(eidx + e + 3);
                    float ra = __ldg(rs_edge + sa), rb = __ldg(rs_edge + sb);
                    float rc = __ldg(rs_edge + sc), rd = __ldg(rs_edge + sd);
                    float4 va = __ldg((const float4*)(X + (long)sa * DD) + lane);
                    float4 vb = __ldg((const float4*)(X + (long)sb * DD) + lane);
                    float4 vc = __ldg((const float4*)(X + (long)sc * DD) + lane);
                    float4 vd = __ldg((const float4*)(X + (long)sd * DD) + lane);
                    acc.x = fmaf(va.x, ra, acc.x); acc.y = fmaf(va.y, ra, acc.y);
                    acc.z = fmaf(va.z, ra, acc.z); acc.w = fmaf(va.w, ra, acc.w);
                    acc.x = fmaf(vb.x, rb, acc.x); acc.y = fmaf(vb.y, rb, acc.y);
                    acc.z = fmaf(vb.z, rb, acc.z); acc.w = fmaf(vb.w, rb, acc.w);
                    acc.x = fmaf(vc.x, rc, acc.x); acc.y = fmaf(vc.y, rc, acc.y);
                    acc.z = fmaf(vc.z, rc, acc.z); acc.w = fmaf(vc.w, rc, acc.w);
                    acc.x = fmaf(vd.x, rd, acc.x); acc.y = fmaf(vd.y, rd, acc.y);
                    acc.z = fmaf(vd.z, rd, acc.z); acc.w = fmaf(vd.w, rd, acc.w);
                }
                for (; e < end; e++) {
                    int sa = __ldg(eidx + e);
                    float ra = __ldg(rs_edge + sa);
                    float4 va = __ldg((const float4*)(X + (long)sa * DD) + lane);
                    acc.x = fmaf(va.x, ra, acc.x); acc.y = fmaf(va.y, ra, acc.y);
                    acc.z = fmaf(va.z, ra, acc.z); acc.w = fmaf(va.w, ra, acc.w);
                }
            } else {
                for (; e + 3 < end; e += 4) {
                    int sa = __ldg(eidx + e),     sb = __ldg(eidx + e + 1);
                    int sc = __ldg(eidx + e + 2), sd = __ldg(eidx + e + 3);
                    float4 va = __ldg((const float4*)(X + (long)sa * DD) + lane);
                    float4 vb = __ldg((const float4*)(X + (long)sb * DD) + lane);
                    float4 vc = __ldg((const float4*)(X + (long)sc * DD) + lane);
                    float4 vd = __ldg((const float4*)(X + (long)sd * DD) + lane);
                    acc.x += (va.x + vb.x) + (vc.x + vd.x);
                    acc.y += (va.y + vb.y) + (vc.y + vd.y);
                    acc.z += (va.z + vb.z) + (vc.z + vd.z);
                    acc.w += (va.w + vb.w) + (vc.w + vd.w);
                }
                for (; e < end; e++) {
                    int sa = __ldg(eidx + e);
                    float4 va = __ldg((const float4*)(X + (long)sa * DD) + lane);
                    acc.x += va.x; acc.y += va.y; acc.z += va.z; acc.w += va.w;
                }
            }
            float rd = __ldg(rs_row + gr);
            acc.x *= rd; acc.y *= rd; acc.z *= rd; acc.w *= rd;
        }
        ((uint2*)(sAhi + row * 68))[lane] =
            make_uint2(packbf(acc.x, acc.y), packbf(acc.z, acc.w));
        ((uint2*)(sAlo + row * 68))[lane] = make_uint2(
            packbf(bfres(acc.x), bfres(acc.y)), packbf(bfres(acc.z), bfres(acc.w)));
    }
    __syncthreads();

    // MMA phase
    int mg = w >> 2, ng = w & 3;
    int tg = lane & 3, gid = lane >> 2;

    float acc[2][4][4];
#pragma unroll
    for (int mi = 0; mi < 2; mi++)
#pragma unroll
        for (int ni = 0; ni < 4; ni++)
#pragma unroll
            for (int q = 0; q < 4; q++) acc[mi][ni][q] = 0.f;

#pragma unroll
    for (int ks = 0; ks < 8; ks++) {
        unsigned Ah[2][4], Al[2][4], Bh[4][2], Bl[4][2];
#pragma unroll
        for (int mi = 0; mi < 2; mi++) {
            int base = (mg * 32 + mi * 16 + gid) * 68 + ks * 8 + tg;
            Ah[mi][0] = sAhi[base];
            Ah[mi][1] = sAhi[base + 8 * 68];
            Ah[mi][2] = sAhi[base + 4];
            Ah[mi][3] = sAhi[base + 8 * 68 + 4];
            Al[mi][0] = sAlo[base];
            Al[mi][1] = sAlo[base + 8 * 68];
            Al[mi][2] = sAlo[base + 4];
            Al[mi][3] = sAlo[base + 8 * 68 + 4];
        }
#pragma unroll
        for (int ni = 0; ni < 4; ni++) {
            int cb = (ng * 32 + ni * 8 + gid) * 68 + ks * 8 + tg;
            Bh[ni][0] = sWhi[cb];
            Bh[ni][1] = sWhi[cb + 4];
            Bl[ni][0] = sWlo[cb];
            Bl[ni][1] = sWlo[cb + 4];
        }
#pragma unroll
        for (int mi = 0; mi < 2; mi++)
#pragma unroll
            for (int ni = 0; ni < 4; ni++) {
                float* d = acc[mi][ni];
                mma_bf16(d[0], d[1], d[2], d[3],
                         Ah[mi][0], Ah[mi][1], Ah[mi][2], Ah[mi][3],
                         Bh[ni][0], Bh[ni][1]);
                mma_bf16(d[0], d[1], d[2], d[3],
                         Ah[mi][0], Ah[mi][1], Ah[mi][2], Ah[mi][3],
                         Bl[ni][0], Bl[ni][1]);
                mma_bf16(d[0], d[1], d[2], d[3],
                         Al[mi][0], Al[mi][1], Al[mi][2], Al[mi][3],
                         Bh[ni][0], Bh[ni][1]);
            }
    }

#pragma unroll
    for (int ni = 0; ni < 4; ni++) {
        int col = ng * 32 + ni * 8 + 2 * tg;
        float bb0 = __ldg(bp + col), bb1 = __ldg(bp + col + 1);
#pragma unroll
        for (int mi = 0; mi < 2; mi++) {
            int gr = r0 + mg * 32 + mi * 16 + gid;
            if (gr < NN) {
                float ro = rso ? __ldg(rso + gr) : 1.f;
                float v0 = acc[mi][ni][0] + bb0;
                float v1 = acc[mi][ni][1] + bb1;
                if (doRelu) { v0 = fmaxf(v0, 0.f); v1 = fmaxf(v1, 0.f); }
                *(float2*)(out + (long)gr * DD + col) = make_float2(v0 * ro, v1 * ro);
            }
            int gr8 = gr + 8;
            if (gr8 < NN) {
                float ro = rso ? __ldg(rso + gr8) : 1.f;
                float v2 = acc[mi][ni][2] + bb0;
                float v3 = acc[mi][ni][3] + bb1;
                if (doRelu) { v2 = fmaxf(v2, 0.f); v3 = fmaxf(v3, 0.f); }
                *(float2*)(out + (long)gr8 * DD + col) = make_float2(v2 * ro, v3 * ro);
            }
        }
    }
}

// ---------------------------------------------------------------------------
// MLP layer1 (unchanged)
__global__ void __launch_bounds__(256, 2) k_mlp1_bf16(
    const float* __restrict__ XA, const float* __restrict__ XB,
    const unsigned* __restrict__ WTm1, float* __restrict__ out,
    float* __restrict__ stat) {
    extern __shared__ unsigned smu[];
    unsigned* sAhi = smu + U_AHI;
    unsigned* sAlo = smu + U_ALO;
    unsigned* sWhi = smu + U_WHI;
    unsigned* sWlo = smu + U_WLO;
    int tid = threadIdx.x;
    int r0 = blockIdx.x * 64;
    int lane = tid & 31, w = tid >> 5;
    int mg = w >> 2, ng = w & 3;
    int tg = lane & 3, gid = lane >> 2;

    float acc[2][4][4];
#pragma unroll
    for (int mi = 0; mi < 2; mi++)
#pragma unroll
        for (int ni = 0; ni < 4; ni++)
#pragma unroll
            for (int q = 0; q < 4; q++) acc[mi][ni][q] = 0.f;

    for (int ph = 0; ph < 2; ph++) {
        const float* X = ph ? XB : XA;
        for (int i = tid; i < 2048; i += 256) {
            int row = i >> 5, f4 = i & 31;
            int gr = r0 + row;
            float4 v = make_float4(0.f, 0.f, 0.f, 0.f);
            if (gr < NN) v = __ldg((const float4*)(X + (long)gr * DD) + f4);
            ((uint2*)(sAhi + row * 68))[f4] = make_uint2(packbf(v.x, v.y), packbf(v.z, v.w));
            ((uint2*)(sAlo + row * 68))[f4] = make_uint2(
                packbf(bfres(v.x), bfres(v.y)), packbf(bfres(v.z), bfres(v.w)));
        }
        for (int i = tid; i < 4096; i += 256) {
            int n = i >> 5, q = i & 31;
            ((uint2*)(sWhi + n * 68))[q] =
                __ldg((const uint2*)(WTm1 + n * 128 + ph * 64) + q);
            ((uint2*)(sWlo + n * 68))[q] =
                __ldg((const uint2*)(WTm1 + 16384 + n * 128 + ph * 64) + q);
        }
        __syncthreads();

#pragma unroll
        for (int ks = 0; ks < 8; ks++) {
            unsigned Ah[2][4], Al[2][4], Bh[4][2], Bl[4][2];
#pragma unroll
            for (int mi = 0; mi < 2; mi++) {
                int base = (mg * 32 + mi * 16 + gid) * 68 + ks * 8 + tg;
                Ah[mi][0] = sAhi[base];
                Ah[mi][1] = sAhi[base + 8 * 68];
                Ah[mi][2] = sAhi[base + 4];
                Ah[mi][3] = sAhi[base + 8 * 68 + 4];
                Al[mi][0] = sAlo[base];
                Al[mi][1] = sAlo[base + 8 * 68];
                Al[mi][2] = sAlo[base + 4];
                Al[mi][3] = sAlo[base + 8 * 68 + 4];
            }
#pragma unroll
            for (int ni = 0; ni < 4; ni++) {
                int cb = (ng * 32 + ni * 8 + gid) * 68 + ks * 8 + tg;
                Bh[ni][0] = sWhi[cb];
                Bh[ni][1] = sWhi[cb + 4];
                Bl[ni][0] = sWlo[cb];
                Bl[ni][1] = sWlo[cb + 4];
            }
#pragma unroll
            for (int mi = 0; mi < 2; mi++)
#pragma unroll
                for (int ni = 0; ni < 4; ni++) {
                    float* d = acc[mi][ni];
                    mma_bf16(d[0], d[1], d[2], d[3],
                             Ah[mi][0], Ah[mi][1], Ah[mi][2], Ah[mi][3],
                             Bh[ni][0], Bh[ni][1]);
                    mma_bf16(d[0], d[1], d[2], d[3],
                             Ah[mi][0], Ah[mi][1], Ah[mi][2], Ah[mi][3],
                             Bl[ni][0], Bl[ni][1]);
                    mma_bf16(d[0], d[1], d[2], d[3],
                             Al[mi][0], Al[mi][1], Al[mi][2], Al[mi][3],
                             Bh[ni][0], Bh[ni][1]);
                }
        }
        __syncthreads();
    }

    float cs[4][2], cq[4][2];
#pragma unroll
    for (int ni = 0; ni < 4; ni++) {
        cs[ni][0] = cs[ni][1] = 0.f;
        cq[ni][0] = cq[ni][1] = 0.f;
    }
#pragma unroll
    for (int ni = 0; ni < 4; ni++) {
        int col = ng * 32 + ni * 8 + 2 * tg;
#pragma unroll
        for (int mi = 0; mi < 2; mi++) {
            int gr = r0 + mg * 32 + mi * 16 + gid;
            if (gr < NN) {
                float v0 = acc[mi][ni][0], v1 = acc[mi][ni][1];
                *(float2*)(out + (long)gr * DD + col) = make_float2(v0, v1);
                cs[ni][0] += v0; cq[ni][0] += v0 * v0;
                cs[ni][1] += v1; cq[ni][1] += v1 * v1;
            }
            int gr8 = gr + 8;
            if (gr8 < NN) {
                float v2 = acc[mi][ni][2], v3 = acc[mi][ni][3];
                *(float2*)(out + (long)gr8 * DD + col) = make_float2(v2, v3);
                cs[ni][0] += v2; cq[ni][0] += v2 * v2;
                cs[ni][1] += v3; cq[ni][1] += v3 * v3;
            }
        }
    }
    __syncthreads();
    float* ssum = (float*)smu;
    float* ssq  = (float*)smu + 128;
    if (tid < 256) ((float*)smu)[tid] = 0.f;
    __syncthreads();
#pragma unroll
    for (int ni = 0; ni < 4; ni++) {
        int col = ng * 32 + ni * 8 + 2 * tg;
        atomicAdd(&ssum[col], cs[ni][0]);
        atomicAdd(&ssum[col + 1], cs[ni][1]);
        atomicAdd(&ssq[col], cq[ni][0]);
        atomicAdd(&ssq[col + 1], cq[ni][1]);
    }
    __syncthreads();
    if (tid < 128) {
        atomicAdd(&stat[tid], ssum[tid]);
        atomicAdd(&stat[128 + tid], ssq[tid]);
    }
}

// ---------------------------------------------------------------------------
__global__ void k_bn_finalize(const float* __restrict__ stat,
                              const float* __restrict__ gamma,
                              const float* __restrict__ beta,
                              float* __restrict__ bn) {
    int c = threadIdx.x;
    if (c < 128) {
        float mu  = stat[c] * (1.f / NN);
        float var = stat[128 + c] * (1.f / NN) - mu * mu;
        float sc  = gamma[c] * rsqrtf(var + 1e-5f);
        bn[c]       = sc;
        bn[128 + c] = beta[c] - mu * sc;
    }
}

__global__ void __launch_bounds__(256) k_mlp2(
    const float* __restrict__ H, const float* __restrict__ bn,
    const float* __restrict__ Wm2, float* __restrict__ out) {
    __shared__ float sw[256];
    __shared__ float sb[256];
    int tid = threadIdx.x;
    if (tid < 256) { sw[tid] = Wm2[tid]; sb[tid] = bn[tid]; }
    __syncthreads();
    int g = blockIdx.x * blockDim.x + tid;
    int row = g >> 5, lane = g & 31;
    if (row >= NN) return;
    float4 h = ((const float4*)(H + (long)row * DD))[lane];
    float s0 = 0.f, s1 = 0.f;
    int c = lane * 4;
    float hv[4] = {h.x, h.y, h.z, h.w};
#pragma unroll
    for (int j = 0; j < 4; j++) {
        int cc = c + j;
        float v = fmaxf(hv[j] * sb[cc] + sb[128 + cc], 0.f);
        s0 += v * sw[cc * 2];
        s1 += v * sw[cc * 2 + 1];
    }
#pragma unroll
    for (int off = 16; off > 0; off >>= 1) {
        s0 += __shfl_down_sync(0xffffffffu, s0, off);
        s1 += __shfl_down_sync(0xffffffffu, s1, off);
    }
    if (lane == 0) {
        out[row * 2]     = s0;
        out[row * 2 + 1] = s1;
    }
}

// ---------------------------------------------------------------------------
extern "C" void kernel_launch(void* const* d_in, const int* in_sizes, int n_in,
                              void* d_out, int out_size) {
    const float* xA    = (const float*)d_in[0];
    const float* xB    = (const float*)d_in[1];
    const int*   s0    = (const int*)d_in[2];
    const int*   d0    = (const int*)d_in[3];
    const int*   s1    = (const int*)d_in[4];
    const int*   d1    = (const int*)d_in[5];
    const float* W1r0  = (const float*)d_in[6];
    const float* b1r0  = (const float*)d_in[7];
    const float* W1r1  = (const float*)d_in[8];
    const float* b1r1  = (const float*)d_in[9];
    const float* W2r0  = (const float*)d_in[10];
    const float* b2r0  = (const float*)d_in[11];
    const float* W2r1  = (const float*)d_in[12];
    const float* b2r1  = (const float*)d_in[13];
    const float* Wm1   = (const float*)d_in[14];
    const float* gamma = (const float*)d_in[15];
    const float* beta  = (const float*)d_in[16];
    const float* Wm2   = (const float*)d_in[17];
    float* out = (float*)d_out;

    float* S = nullptr;
    cudaGetSymbolAddress((void**)&S, g_s);
    int* I = nullptr;
    cudaGetSymbolAddress((void**)&I, g_i);

    float* HB    = S + OFF_HB;
    float* HA    = S + OFF_HA;
    float* H2A   = S + OFF_H2A;
    float* H2B   = S + OFF_H2B;
    float* HMLP  = S + OFF_HMLP;
    float* RS    = S + OFF_RS;
    float* STATS = S + OFF_STATS;
    float* BN    = S + OFF_BN;
    unsigned* WT = (unsigned*)(S + OFF_WT);

    int* eidx0 = I + IOFF_EIDX0;
    int* eidx1 = I + IOFF_EIDX1;
    int* od0   = I + IOFF_OD0;
    int* cnt0  = I + IOFF_CNT0;
    int* od1   = I + IOFF_OD1;
    int* cnt1  = I + IOFF_CNT1;
    int* rp0   = I + IOFF_RP0;
    int* rp1   = I + IOFF_RP1;
    int* cur0  = I + IOFF_CUR0;
    int* cur1  = I + IOFF_CUR1;
    int* bsum  = I + IOFF_BSUM;
    int* pfx   = I + IOFF_PFX;
    int* syn   = I + IOFF_SYNC;

    float* rs_src0 = RS + 0 * NN;
    float* rs_dst0 = RS + 1 * NN;
    float* rs_src1 = RS + 2 * NN;
    float* rs_dst1 = RS + 3 * NN;

    unsigned* W1r0T = WT + 0;
    unsigned* W1r1T = WT + 16384;
    unsigned* W2r0T = WT + 32768;
    unsigned* W2r1T = WT + 49152;
    unsigned* Wm1T  = WT + 65536;

    cudaFuncSetAttribute(k_conv_fused, cudaFuncAttributeMaxDynamicSharedMemorySize, (int)SMEM_G);
    cudaFuncSetAttribute(k_mlp1_bf16,  cudaFuncAttributeMaxDynamicSharedMemorySize, (int)SMEM_G);

    // 1) zero deg histograms + STATS + sync
    k_zero2<<<(NN + 255) / 256, 256>>>(od0, STATS, syn);

    // 2) degree histograms + weight prep
    k_hist<<<(EE + 255) / 256, 256>>>(s0, d0, s1, d1, od0, cnt0, od1, cnt1);
    k_wprep<<<192, 256>>>(W1r0, W1r1, W2r0, W2r1, Wm1, WT);

    // 3) fused scan (rowptr + cursors + rs, one kernel)
    k_scan_fused<<<dim3(NBLK, 2), 256>>>(cnt0, cnt1, od0, od1, bsum, pfx, syn,
                                         rp0, rp1, cur0, cur1, RS);

    // 4) CSR fill
    k_fill<<<(EE + 255) / 256, 256>>>(s0, d0, s1, d1, cur0, eidx0, cur1, eidx1);

    dim3 tgrid((NN + 63) / 64, 2);
    int mgrid = (NN + 63) / 64;

    // 5) conv1 fused (gather+GEMM, both relations; fold next layer's rs_src)
    k_conv_fused<<<tgrid, 256, SMEM_G>>>(
        xA, eidx0, rp0, rs_src0, rs_dst0, W1r0T, b1r0, HB, rs_src1,
        xB, eidx1, rp1, rs_src1, rs_dst1, W1r1T, b1r1, HA, rs_src0,
        1, 1);

    // 6) conv2 fused (sources pre-scaled; no edge rs)
    k_conv_fused<<<tgrid, 256, SMEM_G>>>(
        HA, eidx0, rp0, nullptr, rs_dst0, W2r0T, b2r0, H2B, nullptr,
        HB, eidx1, rp1, nullptr, rs_dst1, W2r1T, b2r1, H2A, nullptr,
        0, 0);

    // 7) MLP layer 1 + BN stats
    k_mlp1_bf16<<<mgrid, 256, SMEM_G>>>(H2A, H2B, Wm1T, HMLP, STATS);

    // 8) BN finalize + 9) head
    k_bn_finalize<<<1, 128>>>(STATS, gamma, beta, BN);
    k_mlp2<<<(NN * 32 + 255) / 256, 256>>>(HMLP, BN, Wm2, out);
}

// round 10
// speedup vs baseline: 1.1254x; 1.1254x over previous
#include <cuda_runtime.h>
#include <cuda_bf16.h>
#include <math.h>

#define NN 50000
#define EE 600000
#define DD 128
#define NF (NN*DD)
#define NBLK 196   // ceil(NN/256)
#define HBLK ((EE + 255) / 256)   // 2344

// ---------------------------------------------------------------------------
// bf16 helpers
__device__ __forceinline__ unsigned packbf(float even, float odd) {
    unsigned d;
    asm("cvt.rn.bf16x2.f32 %0, %1, %2;" : "=r"(d) : "f"(odd), "f"(even));
    return d;
}
__device__ __forceinline__ float bfres(float v) {
    return v - __bfloat162float(__float2bfloat16(v));
}
__device__ __forceinline__ void mma_bf16(
    float& d0, float& d1, float& d2, float& d3,
    unsigned a0, unsigned a1, unsigned a2, unsigned a3,
    unsigned b0, unsigned b1) {
    asm volatile(
        "mma.sync.aligned.m16n8k16.row.col.f32.bf16.bf16.f32 "
        "{%0,%1,%2,%3},{%4,%5,%6,%7},{%8,%9},{%0,%1,%2,%3};"
        : "+f"(d0), "+f"(d1), "+f"(d2), "+f"(d3)
        : "r"(a0), "r"(a1), "r"(a2), "r"(a3), "r"(b0), "r"(b1));
}

// ---------------------------------------------------------------------------
#define OFF_AGG1B 0ULL
#define OFF_AGG1A (1ULL*NF)
#define OFF_AGG2B (2ULL*NF)
#define OFF_AGG2A (3ULL*NF)
#define OFF_HB    (4ULL*NF)
#define OFF_HA    (5ULL*NF)
#define OFF_H2A   (6ULL*NF)
#define OFF_H2B   (7ULL*NF)
#define OFF_HMLP  (8ULL*NF)
#define OFF_RS    (9ULL*NF)
#define OFF_STATS (9ULL*NF + 4ULL*NN)
#define OFF_BN    (OFF_STATS + 256ULL)
#define OFF_WT    (OFF_BN + 256ULL)
#define SCRATCH_FLOATS (OFF_WT + 196608ULL)

__device__ __align__(256) float g_s[SCRATCH_FLOATS];

#define IOFF_EIDX0 0
#define IOFF_EIDX1 (EE)
#define IOFF_OD0   (2*EE)
#define IOFF_CNT0  (2*EE + NN)
#define IOFF_OD1   (2*EE + 2*NN)
#define IOFF_CNT1  (2*EE + 3*NN)
#define IOFF_RP0   (2*EE + 4*NN)
#define IOFF_RP1   (2*EE + 5*NN + 1)
#define IOFF_CUR0  (2*EE + 6*NN + 2)
#define IOFF_CUR1  (2*EE + 7*NN + 2)
#define IOFF_BSUM  (2*EE + 8*NN + 2)
#define IOFF_PFX   (IOFF_BSUM + 2*NBLK)
#define IOFF_SYNC  (IOFF_PFX + 2*NBLK)      // [0]=scan arrivals,[1]=scan flag,[2]=mlp1 arrivals
#define SCRATCH_INTS (IOFF_SYNC + 4)

__device__ __align__(256) int g_i[SCRATCH_INTS];

// ---------------------------------------------------------------------------
__global__ void k_zero2(int* __restrict__ deg, float* __restrict__ stats,
                        int* __restrict__ syn) {
    int i = blockIdx.x * 256 + threadIdx.x;
    if (i < NN) ((int4*)deg)[i] = make_int4(0, 0, 0, 0);   // 4*NN ints
    if (i < 64) ((float4*)stats)[i] = make_float4(0.f, 0.f, 0.f, 0.f);
    if (i < 4) syn[i] = 0;
}

// hist + wprep merged: blocks [0,HBLK) histogram; blocks [HBLK,HBLK+192) wprep
__global__ void k_hist_wprep(
    const int* __restrict__ s0, const int* __restrict__ d0,
    const int* __restrict__ s1, const int* __restrict__ d1,
    int* __restrict__ od0, int* __restrict__ cnt0,
    int* __restrict__ od1, int* __restrict__ cnt1,
    const float* __restrict__ W1r0, const float* __restrict__ W1r1,
    const float* __restrict__ W2r0, const float* __restrict__ W2r1,
    const float* __restrict__ Wm1, unsigned* __restrict__ WT) {
    if (blockIdx.x < HBLK) {
        int i = blockIdx.x * 256 + threadIdx.x;
        if (i < EE) {
            atomicAdd(&od0[s0[i]], 1);
            atomicAdd(&cnt0[d0[i]], 1);
            atomicAdd(&od1[s1[i]], 1);
            atomicAdd(&cnt1[d1[i]], 1);
        }
    } else {
        int idx = (blockIdx.x - HBLK) * 256 + threadIdx.x;
        if (idx < 32768) {
            int mat = idx >> 13, r = idx & 8191;
            int n = r >> 6, ku = r & 63;
            int k = 2 * ku;
            const float* Wsrc = (mat == 0) ? W1r0 : (mat == 1) ? W1r1 :
                                (mat == 2) ? W2r0 : W2r1;
            float v0 = __ldg(Wsrc + k * 128 + n);
            float v1 = __ldg(Wsrc + (k + 1) * 128 + n);
            WT[mat * 16384 + n * 64 + ku]        = packbf(v0, v1);
            WT[mat * 16384 + 8192 + n * 64 + ku] = packbf(bfres(v0), bfres(v1));
        } else if (idx < 49152) {
            int r = idx - 32768;
            int n = r >> 7, ku = r & 127;
            int k = 2 * ku;
            float v0 = __ldg(Wm1 + k * 128 + n);
            float v1 = __ldg(Wm1 + (k + 1) * 128 + n);
            WT[65536 + n * 128 + ku]         = packbf(v0, v1);
            WT[65536 + 16384 + n * 128 + ku] = packbf(bfres(v0), bfres(v1));
        }
    }
}

// fused scan (R7/R9-verified): block sums -> last block scans -> rowptr/cursor/rs
__global__ void __launch_bounds__(256) k_scan_fused(
    const int* __restrict__ c0, const int* __restrict__ c1,
    const int* __restrict__ od0, const int* __restrict__ od1,
    int* __restrict__ bsum, int* __restrict__ pfx, int* __restrict__ syn,
    int* __restrict__ rp0, int* __restrict__ rp1,
    int* __restrict__ cur0, int* __restrict__ cur1,
    float* __restrict__ rs) {
    __shared__ int sp[256];
    __shared__ int sp2[512];
    __shared__ int islast;
    int t = threadIdx.x;
    int y = blockIdx.y;
    const int* cnt = y ? c1 : c0;
    const int* od  = y ? od1 : od0;
    int* rp  = y ? rp1 : rp0;
    int* cur = y ? cur1 : cur0;
    int i = blockIdx.x * 256 + t;
    int v = (i < NN) ? cnt[i] : 0;

    sp[t] = v;
    __syncthreads();
    for (int off = 128; off; off >>= 1) {
        if (t < off) sp[t] += sp[t + off];
        __syncthreads();
    }
    if (t == 0) {
        bsum[y * NBLK + blockIdx.x] = sp[0];
        __threadfence();
        int old = atomicAdd(&syn[0], 1);
        islast = (old == 2 * NBLK - 1);
    }
    __syncthreads();

    if (islast) {
        for (int j = t; j < 2 * NBLK; j += 256) sp2[j] = ((volatile int*)bsum)[j];
        __syncthreads();
        for (int rel = 0; rel < 2; rel++) {
            int* a = sp2 + rel * NBLK;
            int mine = (t < NBLK) ? a[t] : 0;
            sp[t] = mine;
            __syncthreads();
            for (int off = 1; off < 256; off <<= 1) {
                int u = (t >= off) ? sp[t - off] : 0;
                __syncthreads();
                sp[t] += u;
                __syncthreads();
            }
            if (t < NBLK) pfx[rel * NBLK + t] = sp[t] - mine;
            __syncthreads();
        }
        if (t == 0) {
            __threadfence();
            atomicExch(&syn[1], 1);
        }
    }
    if (t == 0) {
        while (((volatile int*)syn)[1] == 0) __nanosleep(64);
    }
    __syncthreads();

    sp[t] = v;
    __syncthreads();
    for (int off = 1; off < 256; off <<= 1) {
        int u = (t >= off) ? sp[t - off] : 0;
        __syncthreads();
        sp[t] += u;
        __syncthreads();
    }
    if (i < NN) {
        int ex = sp[t] - v + ((volatile int*)pfx)[y * NBLK + blockIdx.x];
        rp[i] = ex;
        cur[i] = ex;
        rs[(2 * y + 0) * NN + i] = rsqrtf((float)max(od[i], 1));
        rs[(2 * y + 1) * NN + i] = rsqrtf((float)max(v, 1));
    }
    if (i == NN - 1) rp[NN] = EE;
}

__global__ void k_fill(const int* __restrict__ s0, const int* __restrict__ d0,
                       const int* __restrict__ s1, const int* __restrict__ d1,
                       int* __restrict__ cur0, int* __restrict__ eidx0,
                       int* __restrict__ cur1, int* __restrict__ eidx1) {
    int i = blockIdx.x * blockDim.x + threadIdx.x;
    if (i < EE) {
        int p0 = atomicAdd(&cur0[d0[i]], 1);
        eidx0[p0] = s0[i];
        int p1 = atomicAdd(&cur1[d1[i]], 1);
        eidx1[p1] = s1[i];
    }
}

// ---------------------------------------------------------------------------
// merged gather (R8-exact): 32-reg budget, 8 blocks/SM, x2-unrolled
__global__ void __launch_bounds__(256, 8) k_gather2(
    const float* __restrict__ xa, const int* __restrict__ ea,
    const int* __restrict__ rpa, const float* __restrict__ rsa,
    float* __restrict__ agga,
    const float* __restrict__ xb, const int* __restrict__ eb,
    const int* __restrict__ rpb, const float* __restrict__ rsb,
    float* __restrict__ aggb, int useRs) {
    const float* x  = blockIdx.y ? xb : xa;
    const int* eidx = blockIdx.y ? eb : ea;
    const int* rowptr = blockIdx.y ? rpb : rpa;
    const float* rs_src = blockIdx.y ? rsb : rsa;
    float* agg = blockIdx.y ? aggb : agga;

    int g = blockIdx.x * blockDim.x + threadIdx.x;
    int r = g >> 5, lane = g & 31;
    if (r >= NN) return;
    int beg = __ldg(rowptr + r), end = __ldg(rowptr + r + 1);
    float4 acc = make_float4(0.f, 0.f, 0.f, 0.f);
    int e = beg;
    if (useRs) {
        for (; e + 1 < end; e += 2) {
            int sa = __ldg(eidx + e), sb = __ldg(eidx + e + 1);
            float ra = __ldg(rs_src + sa), rb = __ldg(rs_src + sb);
            float4 va = __ldg((const float4*)(x + (long)sa * DD) + lane);
            float4 vb = __ldg((const float4*)(x + (long)sb * DD) + lane);
            acc.x = fmaf(va.x, ra, acc.x); acc.y = fmaf(va.y, ra, acc.y);
            acc.z = fmaf(va.z, ra, acc.z); acc.w = fmaf(va.w, ra, acc.w);
            acc.x = fmaf(vb.x, rb, acc.x); acc.y = fmaf(vb.y, rb, acc.y);
            acc.z = fmaf(vb.z, rb, acc.z); acc.w = fmaf(vb.w, rb, acc.w);
        }
        if (e < end) {
            int sa = __ldg(eidx + e);
            float ra = __ldg(rs_src + sa);
            float4 va = __ldg((const float4*)(x + (long)sa * DD) + lane);
            acc.x = fmaf(va.x, ra, acc.x); acc.y = fmaf(va.y, ra, acc.y);
            acc.z = fmaf(va.z, ra, acc.z); acc.w = fmaf(va.w, ra, acc.w);
        }
    } else {
        for (; e + 1 < end; e += 2) {
            int sa = __ldg(eidx + e), sb = __ldg(eidx + e + 1);
            float4 va = __ldg((const float4*)(x + (long)sa * DD) + lane);
            float4 vb = __ldg((const float4*)(x + (long)sb * DD) + lane);
            acc.x += va.x + vb.x; acc.y += va.y + vb.y;
            acc.z += va.z + vb.z; acc.w += va.w + vb.w;
        }
        if (e < end) {
            int sa = __ldg(eidx + e);
            float4 va = __ldg((const float4*)(x + (long)sa * DD) + lane);
            acc.x += va.x; acc.y += va.y; acc.z += va.z; acc.w += va.w;
        }
    }
    ((float4*)(agg + (long)r * DD))[lane] = acc;
}

// ---------------------------------------------------------------------------
// bf16x3 tensor-core GEMM (R8-exact)
#define U_AHI 0
#define U_ALO 4352
#define U_WHI 8704
#define U_WLO 17408
#define SMEM_G ((size_t)26112 * 4)

__global__ void __launch_bounds__(256, 2) k_gemm_bf16(
    const float* __restrict__ X0, const float* __restrict__ rsi0,
    const unsigned* __restrict__ Wp0, const float* __restrict__ bp0,
    float* __restrict__ out0, const float* __restrict__ rso0,
    const float* __restrict__ X1, const float* __restrict__ rsi1,
    const unsigned* __restrict__ Wp1, const float* __restrict__ bp1,
    float* __restrict__ out1, const float* __restrict__ rso1,
    int doRelu) {
    extern __shared__ unsigned smu[];
    unsigned* sAhi = smu + U_AHI;
    unsigned* sAlo = smu + U_ALO;
    unsigned* sWhi = smu + U_WHI;
    unsigned* sWlo = smu + U_WLO;

    const float* X = blockIdx.y ? X1 : X0;
    const float* rsi = blockIdx.y ? rsi1 : rsi0;
    const unsigned* Wp = blockIdx.y ? Wp1 : Wp0;
    const float* bp = blockIdx.y ? bp1 : bp0;
    float* out = blockIdx.y ? out1 : out0;
    const float* rso = blockIdx.y ? rso1 : rso0;

    int tid = threadIdx.x;
    int r0 = blockIdx.x * 64;

    for (int i = tid; i < 2048; i += 256) {
        int row = i >> 5, f4 = i & 31;
        int gr = r0 + row;
        float4 v = make_float4(0.f, 0.f, 0.f, 0.f);
        if (gr < NN) {
            v = __ldg((const float4*)(X + (long)gr * DD) + f4);
            float r = __ldg(rsi + gr);
            v.x *= r; v.y *= r; v.z *= r; v.w *= r;
        }
        ((uint2*)(sAhi + row * 68))[f4] = make_uint2(packbf(v.x, v.y), packbf(v.z, v.w));
        ((uint2*)(sAlo + row * 68))[f4] = make_uint2(
            packbf(bfres(v.x), bfres(v.y)), packbf(bfres(v.z), bfres(v.w)));
    }
    for (int i = tid; i < 4096; i += 256) {
        int n = i >> 5, q = i & 31;
        ((uint2*)(sWhi + n * 68))[q] = __ldg((const uint2*)(Wp + n * 64) + q);
        ((uint2*)(sWlo + n * 68))[q] = __ldg((const uint2*)(Wp + 8192 + n * 64) + q);
    }
    __syncthreads();

    int lane = tid & 31, w = tid >> 5;
    int mg = w >> 2, ng = w & 3;
    int tg = lane & 3, gid = lane >> 2;

    float acc[2][4][4];
#pragma unroll
    for (int mi = 0; mi < 2; mi++)
#pragma unroll
        for (int ni = 0; ni < 4; ni++)
#pragma unroll
            for (int q = 0; q < 4; q++) acc[mi][ni][q] = 0.f;

#pragma unroll
    for (int ks = 0; ks < 8; ks++) {
        unsigned Ah[2][4], Al[2][4], Bh[4][2], Bl[4][2];
#pragma unroll
        for (int mi = 0; mi < 2; mi++) {
            int base = (mg * 32 + mi * 16 + gid) * 68 + ks * 8 + tg;
            Ah[mi][0] = sAhi[base];
            Ah[mi][1] = sAhi[base + 8 * 68];
            Ah[mi][2] = sAhi[base + 4];
            Ah[mi][3] = sAhi[base + 8 * 68 + 4];
            Al[mi][0] = sAlo[base];
            Al[mi][1] = sAlo[base + 8 * 68];
            Al[mi][2] = sAlo[base + 4];
            Al[mi][3] = sAlo[base + 8 * 68 + 4];
        }
#pragma unroll
        for (int ni = 0; ni < 4; ni++) {
            int cb = (ng * 32 + ni * 8 + gid) * 68 + ks * 8 + tg;
            Bh[ni][0] = sWhi[cb];
            Bh[ni][1] = sWhi[cb + 4];
            Bl[ni][0] = sWlo[cb];
            Bl[ni][1] = sWlo[cb + 4];
        }
#pragma unroll
        for (int mi = 0; mi < 2; mi++)
#pragma unroll
            for (int ni = 0; ni < 4; ni++) {
                float* d = acc[mi][ni];
                mma_bf16(d[0], d[1], d[2], d[3],
                         Ah[mi][0], Ah[mi][1], Ah[mi][2], Ah[mi][3],
                         Bh[ni][0], Bh[ni][1]);
                mma_bf16(d[0], d[1], d[2], d[3],
                         Ah[mi][0], Ah[mi][1], Ah[mi][2], Ah[mi][3],
                         Bl[ni][0], Bl[ni][1]);
                mma_bf16(d[0], d[1], d[2], d[3],
                         Al[mi][0], Al[mi][1], Al[mi][2], Al[mi][3],
                         Bh[ni][0], Bh[ni][1]);
            }
    }

#pragma unroll
    for (int ni = 0; ni < 4; ni++) {
        int col = ng * 32 + ni * 8 + 2 * tg;
        float bb0 = __ldg(bp + col), bb1 = __ldg(bp + col + 1);
#pragma unroll
        for (int mi = 0; mi < 2; mi++) {
            int gr = r0 + mg * 32 + mi * 16 + gid;
            if (gr < NN) {
                float ro = rso ? __ldg(rso + gr) : 1.f;
                float v0 = acc[mi][ni][0] + bb0;
                float v1 = acc[mi][ni][1] + bb1;
                if (doRelu) { v0 = fmaxf(v0, 0.f); v1 = fmaxf(v1, 0.f); }
                *(float2*)(out + (long)gr * DD + col) = make_float2(v0 * ro, v1 * ro);
            }
            int gr8 = gr + 8;
            if (gr8 < NN) {
                float ro = rso ? __ldg(rso + gr8) : 1.f;
                float v2 = acc[mi][ni][2] + bb0;
                float v3 = acc[mi][ni][3] + bb1;
                if (doRelu) { v2 = fmaxf(v2, 0.f); v3 = fmaxf(v3, 0.f); }
                *(float2*)(out + (long)gr8 * DD + col) = make_float2(v2 * ro, v3 * ro);
            }
        }
    }
}

// ---------------------------------------------------------------------------
// MLP layer1 + BN stats + (NEW) last-block BN finalize
__global__ void __launch_bounds__(256, 2) k_mlp1_bf16(
    const float* __restrict__ XA, const float* __restrict__ XB,
    const unsigned* __restrict__ WTm1, float* __restrict__ out,
    float* __restrict__ stat, int* __restrict__ syn,
    const float* __restrict__ gamma, const float* __restrict__ beta,
    float* __restrict__ bn) {
    extern __shared__ unsigned smu[];
    unsigned* sAhi = smu + U_AHI;
    unsigned* sAlo = smu + U_ALO;
    unsigned* sWhi = smu + U_WHI;
    unsigned* sWlo = smu + U_WLO;
    int tid = threadIdx.x;
    int r0 = blockIdx.x * 64;
    int lane = tid & 31, w = tid >> 5;
    int mg = w >> 2, ng = w & 3;
    int tg = lane & 3, gid = lane >> 2;

    float acc[2][4][4];
#pragma unroll
    for (int mi = 0; mi < 2; mi++)
#pragma unroll
        for (int ni = 0; ni < 4; ni++)
#pragma unroll
            for (int q = 0; q < 4; q++) acc[mi][ni][q] = 0.f;

    for (int ph = 0; ph < 2; ph++) {
        const float* X = ph ? XB : XA;
        for (int i = tid; i < 2048; i += 256) {
            int row = i >> 5, f4 = i & 31;
            int gr = r0 + row;
            float4 v = make_float4(0.f, 0.f, 0.f, 0.f);
            if (gr < NN) v = __ldg((const float4*)(X + (long)gr * DD) + f4);
            ((uint2*)(sAhi + row * 68))[f4] = make_uint2(packbf(v.x, v.y), packbf(v.z, v.w));
            ((uint2*)(sAlo + row * 68))[f4] = make_uint2(
                packbf(bfres(v.x), bfres(v.y)), packbf(bfres(v.z), bfres(v.w)));
        }
        for (int i = tid; i < 4096; i += 256) {
            int n = i >> 5, q = i & 31;
            ((uint2*)(sWhi + n * 68))[q] =
                __ldg((const uint2*)(WTm1 + n * 128 + ph * 64) + q);
            ((uint2*)(sWlo + n * 68))[q] =
                __ldg((const uint2*)(WTm1 + 16384 + n * 128 + ph * 64) + q);
        }
        __syncthreads();

#pragma unroll
        for (int ks = 0; ks < 8; ks++) {
            unsigned Ah[2][4], Al[2][4], Bh[4][2], Bl[4][2];
#pragma unroll
            for (int mi = 0; mi < 2; mi++) {
                int base = (mg * 32 + mi * 16 + gid) * 68 + ks * 8 + tg;
                Ah[mi][0] = sAhi[base];
                Ah[mi][1] = sAhi[base + 8 * 68];
                Ah[mi][2] = sAhi[base + 4];
                Ah[mi][3] = sAhi[base + 8 * 68 + 4];
                Al[mi][0] = sAlo[base];
                Al[mi][1] = sAlo[base + 8 * 68];
                Al[mi][2] = sAlo[base + 4];
                Al[mi][3] = sAlo[base + 8 * 68 + 4];
            }
#pragma unroll
            for (int ni = 0; ni < 4; ni++) {
                int cb = (ng * 32 + ni * 8 + gid) * 68 + ks * 8 + tg;
                Bh[ni][0] = sWhi[cb];
                Bh[ni][1] = sWhi[cb + 4];
                Bl[ni][0] = sWlo[cb];
                Bl[ni][1] = sWlo[cb + 4];
            }
#pragma unroll
            for (int mi = 0; mi < 2; mi++)
#pragma unroll
                for (int ni = 0; ni < 4; ni++) {
                    float* d = acc[mi][ni];
                    mma_bf16(d[0], d[1], d[2], d[3],
                             Ah[mi][0], Ah[mi][1], Ah[mi][2], Ah[mi][3],
                             Bh[ni][0], Bh[ni][1]);
                    mma_bf16(d[0], d[1], d[2], d[3],
                             Ah[mi][0], Ah[mi][1], Ah[mi][2], Ah[mi][3],
                             Bl[ni][0], Bl[ni][1]);
                    mma_bf16(d[0], d[1], d[2], d[3],
                             Al[mi][0], Al[mi][1], Al[mi][2], Al[mi][3],
                             Bh[ni][0], Bh[ni][1]);
                }
        }
        __syncthreads();
    }

    float cs[4][2], cq[4][2];
#pragma unroll
    for (int ni = 0; ni < 4; ni++) {
        cs[ni][0] = cs[ni][1] = 0.f;
        cq[ni][0] = cq[ni][1] = 0.f;
    }
#pragma unroll
    for (int ni = 0; ni < 4; ni++) {
        int col = ng * 32 + ni * 8 + 2 * tg;
#pragma unroll
        for (int mi = 0; mi < 2; mi++) {
            int gr = r0 + mg * 32 + mi * 16 + gid;
            if (gr < NN) {
                float v0 = acc[mi][ni][0], v1 = acc[mi][ni][1];
                *(float2*)(out + (long)gr * DD + col) = make_float2(v0, v1);
                cs[ni][0] += v0; cq[ni][0] += v0 * v0;
                cs[ni][1] += v1; cq[ni][1] += v1 * v1;
            }
            int gr8 = gr + 8;
            if (gr8 < NN) {
                float v2 = acc[mi][ni][2], v3 = acc[mi][ni][3];
                *(float2*)(out + (long)gr8 * DD + col) = make_float2(v2, v3);
                cs[ni][0] += v2; cq[ni][0] += v2 * v2;
                cs[ni][1] += v3; cq[ni][1] += v3 * v3;
            }
        }
    }
    __syncthreads();
    float* ssum = (float*)smu;
    float* ssq  = (float*)smu + 128;
    if (tid < 256) ((float*)smu)[tid] = 0.f;
    __syncthreads();
#pragma unroll
    for (int ni = 0; ni < 4; ni++) {
        int col = ng * 32 + ni * 8 + 2 * tg;
        atomicAdd(&ssum[col], cs[ni][0]);
        atomicAdd(&ssum[col + 1], cs[ni][1]);
        atomicAdd(&ssq[col], cq[ni][0]);
        atomicAdd(&ssq[col + 1], cq[ni][1]);
    }
    __syncthreads();
    if (tid < 128) {
        atomicAdd(&stat[tid], ssum[tid]);
        atomicAdd(&stat[128 + tid], ssq[tid]);
    }

    // last-arriving block computes BN scale/shift
    __shared__ int lastblk;
    __threadfence();
    __syncthreads();
    if (tid == 0) {
        int old = atomicAdd(&syn[2], 1);
        lastblk = (old == (int)gridDim.x - 1);
    }
    __syncthreads();
    if (lastblk && tid < 128) {
        float s  = atomicAdd(&stat[tid], 0.f);        // coherent read via L2
        float sq = atomicAdd(&stat[128 + tid], 0.f);
        float mu  = s * (1.f / NN);
        float var = sq * (1.f / NN) - mu * mu;
        float sc  = __ldg(gamma + tid) * rsqrtf(var + 1e-5f);
        bn[tid]       = sc;
        bn[128 + tid] = __ldg(beta + tid) - mu * sc;
    }
}

// ---------------------------------------------------------------------------
__global__ void __launch_bounds__(256) k_mlp2(
    const float* __restrict__ H, const float* __restrict__ bn,
    const float* __restrict__ Wm2, float* __restrict__ out) {
    __shared__ float sw[256];
    __shared__ float sb[256];
    int tid = threadIdx.x;
    if (tid < 256) { sw[tid] = Wm2[tid]; sb[tid] = bn[tid]; }
    __syncthreads();
    int g = blockIdx.x * blockDim.x + tid;
    int row = g >> 5, lane = g & 31;
    if (row >= NN) return;
    float4 h = ((const float4*)(H + (long)row * DD))[lane];
    float s0 = 0.f, s1 = 0.f;
    int c = lane * 4;
    float hv[4] = {h.x, h.y, h.z, h.w};
#pragma unroll
    for (int j = 0; j < 4; j++) {
        int cc = c + j;
        float v = fmaxf(hv[j] * sb[cc] + sb[128 + cc], 0.f);
        s0 += v * sw[cc * 2];
        s1 += v * sw[cc * 2 + 1];
    }
#pragma unroll
    for (int off = 16; off > 0; off >>= 1) {
        s0 += __shfl_down_sync(0xffffffffu, s0, off);
        s1 += __shfl_down_sync(0xffffffffu, s1, off);
    }
    if (lane == 0) {
        out[row * 2]     = s0;
        out[row * 2 + 1] = s1;
    }
}

// ---------------------------------------------------------------------------
extern "C" void kernel_launch(void* const* d_in, const int* in_sizes, int n_in,
                              void* d_out, int out_size) {
    const float* xA    = (const float*)d_in[0];
    const float* xB    = (const float*)d_in[1];
    const int*   s0    = (const int*)d_in[2];
    const int*   d0    = (const int*)d_in[3];
    const int*   s1    = (const int*)d_in[4];
    const int*   d1    = (const int*)d_in[5];
    const float* W1r0  = (const float*)d_in[6];
    const float* b1r0  = (const float*)d_in[7];
    const float* W1r1  = (const float*)d_in[8];
    const float* b1r1  = (const float*)d_in[9];
    const float* W2r0  = (const float*)d_in[10];
    const float* b2r0  = (const float*)d_in[11];
    const float* W2r1  = (const float*)d_in[12];
    const float* b2r1  = (const float*)d_in[13];
    const float* Wm1   = (const float*)d_in[14];
    const float* gamma = (const float*)d_in[15];
    const float* beta  = (const float*)d_in[16];
    const float* Wm2   = (const float*)d_in[17];
    float* out = (float*)d_out;

    float* S = nullptr;
    cudaGetSymbolAddress((void**)&S, g_s);
    int* I = nullptr;
    cudaGetSymbolAddress((void**)&I, g_i);

    float* AGG1B = S + OFF_AGG1B;
    float* AGG1A = S + OFF_AGG1A;
    float* AGG2B = S + OFF_AGG2B;
    float* AGG2A = S + OFF_AGG2A;
    float* HB    = S + OFF_HB;
    float* HA    = S + OFF_HA;
    float* H2A   = S + OFF_H2A;
    float* H2B   = S + OFF_H2B;
    float* HMLP  = S + OFF_HMLP;
    float* RS    = S + OFF_RS;
    float* STATS = S + OFF_STATS;
    float* BN    = S + OFF_BN;
    unsigned* WT = (unsigned*)(S + OFF_WT);

    int* eidx0 = I + IOFF_EIDX0;
    int* eidx1 = I + IOFF_EIDX1;
    int* od0   = I + IOFF_OD0;
    int* cnt0  = I + IOFF_CNT0;
    int* od1   = I + IOFF_OD1;
    int* cnt1  = I + IOFF_CNT1;
    int* rp0   = I + IOFF_RP0;
    int* rp1   = I + IOFF_RP1;
    int* cur0  = I + IOFF_CUR0;
    int* cur1  = I + IOFF_CUR1;
    int* bsum  = I + IOFF_BSUM;
    int* pfx   = I + IOFF_PFX;
    int* syn   = I + IOFF_SYNC;

    float* rs_src0 = RS + 0 * NN;
    float* rs_dst0 = RS + 1 * NN;
    float* rs_src1 = RS + 2 * NN;
    float* rs_dst1 = RS + 3 * NN;

    unsigned* W1r0T = WT + 0;
    unsigned* W1r1T = WT + 16384;
    unsigned* W2r0T = WT + 32768;
    unsigned* W2r1T = WT + 49152;
    unsigned* Wm1T  = WT + 65536;

    cudaFuncSetAttribute(k_gemm_bf16, cudaFuncAttributeMaxDynamicSharedMemorySize, (int)SMEM_G);
    cudaFuncSetAttribute(k_mlp1_bf16, cudaFuncAttributeMaxDynamicSharedMemorySize, (int)SMEM_G);

    // 1) zero deg histograms + STATS + sync words
    k_zero2<<<(NN + 255) / 256, 256>>>(od0, STATS, syn);

    // 2) degree histograms + weight prep (one launch)
    k_hist_wprep<<<HBLK + 192, 256>>>(s0, d0, s1, d1, od0, cnt0, od1, cnt1,
                                      W1r0, W1r1, W2r0, W2r1, Wm1, WT);

    // 3) fused scan (rowptr + cursors + rs)
    k_scan_fused<<<dim3(NBLK, 2), 256>>>(cnt0, cnt1, od0, od1, bsum, pfx, syn,
                                         rp0, rp1, cur0, cur1, RS);

    // 4) CSR fill
    k_fill<<<(EE + 255) / 256, 256>>>(s0, d0, s1, d1, cur0, eidx0, cur1, eidx1);

    dim3 ggrid((NN * 32 + 255) / 256, 2);
    dim3 tgrid((NN + 63) / 64, 2);
    int mgrid = (NN + 63) / 64;

    // 5) conv1 gathers
    k_gather2<<<ggrid, 256>>>(xA, eidx0, rp0, rs_src0, AGG1B,
                              xB, eidx1, rp1, rs_src1, AGG1A, 1);

    // 6) conv1 GEMMs
    k_gemm_bf16<<<tgrid, 256, SMEM_G>>>(
        AGG1B, rs_dst0, W1r0T, b1r0, HB, rs_src1,
        AGG1A, rs_dst1, W1r1T, b1r1, HA, rs_src0, 1);

    // 7) conv2 gathers
    k_gather2<<<ggrid, 256>>>(HA, eidx0, rp0, nullptr, AGG2B,
                              HB, eidx1, rp1, nullptr, AGG2A, 0);

    // 8) conv2 GEMMs
    k_gemm_bf16<<<tgrid, 256, SMEM_G>>>(
        AGG2B, rs_dst0, W2r0T, b2r0, H2B, nullptr,
        AGG2A, rs_dst1, W2r1T, b2r1, H2A, nullptr, 0);

    // 9) MLP layer 1 + BN stats + BN finalize (fused)
    k_mlp1_bf16<<<mgrid, 256, SMEM_G>>>(H2A, H2B, Wm1T, HMLP, STATS, syn,
                                        gamma, beta, BN);

    // 10) head
    k_mlp2<<<(NN * 32 + 255) / 256, 256>>>(HMLP, BN, Wm2, out);
}

// round 11
// speedup vs baseline: 1.1444x; 1.0168x over previous
#include <cuda_runtime.h>
#include <cuda_bf16.h>
#include <math.h>

#define NN 50000
#define EE 600000
#define DD 128
#define NF (NN*DD)
#define NBLK 196   // ceil(NN/256)
#define HBLK ((EE + 255) / 256)   // 2344

// ---------------------------------------------------------------------------
// bf16 helpers
__device__ __forceinline__ unsigned packbf(float even, float odd) {
    unsigned d;
    asm("cvt.rn.bf16x2.f32 %0, %1, %2;" : "=r"(d) : "f"(odd), "f"(even));
    return d;
}
__device__ __forceinline__ float bfres(float v) {
    return v - __bfloat162float(__float2bfloat16(v));
}
__device__ __forceinline__ void mma_bf16(
    float& d0, float& d1, float& d2, float& d3,
    unsigned a0, unsigned a1, unsigned a2, unsigned a3,
    unsigned b0, unsigned b1) {
    asm volatile(
        "mma.sync.aligned.m16n8k16.row.col.f32.bf16.bf16.f32 "
        "{%0,%1,%2,%3},{%4,%5,%6,%7},{%8,%9},{%0,%1,%2,%3};"
        : "+f"(d0), "+f"(d1), "+f"(d2), "+f"(d3)
        : "r"(a0), "r"(a1), "r"(a2), "r"(a3), "r"(b0), "r"(b1));
}

// ---------------------------------------------------------------------------
#define OFF_AGG1B 0ULL
#define OFF_AGG1A (1ULL*NF)
#define OFF_AGG2B (2ULL*NF)
#define OFF_AGG2A (3ULL*NF)
#define OFF_HB    (4ULL*NF)
#define OFF_HA    (5ULL*NF)
#define OFF_H2A   (6ULL*NF)
#define OFF_H2B   (7ULL*NF)
#define OFF_HMLP  (8ULL*NF)
#define OFF_RS    (9ULL*NF)
#define OFF_STATS (9ULL*NF + 4ULL*NN)
#define OFF_BN    (OFF_STATS + 256ULL)
#define OFF_WT    (OFF_BN + 256ULL)
#define SCRATCH_FLOATS (OFF_WT + 196608ULL)

__device__ __align__(256) float g_s[SCRATCH_FLOATS];

#define IOFF_EIDX0 0
#define IOFF_EIDX1 (EE)
#define IOFF_OD0   (2*EE)
#define IOFF_CNT0  (2*EE + NN)
#define IOFF_OD1   (2*EE + 2*NN)
#define IOFF_CNT1  (2*EE + 3*NN)
#define IOFF_RP0   (2*EE + 4*NN)
#define IOFF_RP1   (2*EE + 5*NN + 1)
#define IOFF_CUR0  (2*EE + 6*NN + 2)
#define IOFF_CUR1  (2*EE + 7*NN + 2)
#define IOFF_BSUM  (2*EE + 8*NN + 2)
#define IOFF_PFX   (IOFF_BSUM + 2*NBLK)
#define IOFF_SYNC  (IOFF_PFX + 2*NBLK)      // [0]=scan arrivals,[1]=scan flag,[2]=mlp1 arrivals
#define SCRATCH_INTS (IOFF_SYNC + 4)

__device__ __align__(256) int g_i[SCRATCH_INTS];

// ---------------------------------------------------------------------------
__global__ void k_zero2(int* __restrict__ deg, float* __restrict__ stats,
                        int* __restrict__ syn) {
    int i = blockIdx.x * 256 + threadIdx.x;
    if (i < NN) ((int4*)deg)[i] = make_int4(0, 0, 0, 0);   // 4*NN ints
    if (i < 64) ((float4*)stats)[i] = make_float4(0.f, 0.f, 0.f, 0.f);
    if (i < 4) syn[i] = 0;
}

// hist + wprep merged
__global__ void k_hist_wprep(
    const int* __restrict__ s0, const int* __restrict__ d0,
    const int* __restrict__ s1, const int* __restrict__ d1,
    int* __restrict__ od0, int* __restrict__ cnt0,
    int* __restrict__ od1, int* __restrict__ cnt1,
    const float* __restrict__ W1r0, const float* __restrict__ W1r1,
    const float* __restrict__ W2r0, const float* __restrict__ W2r1,
    const float* __restrict__ Wm1, unsigned* __restrict__ WT) {
    if (blockIdx.x < HBLK) {
        int i = blockIdx.x * 256 + threadIdx.x;
        if (i < EE) {
            atomicAdd(&od0[s0[i]], 1);
            atomicAdd(&cnt0[d0[i]], 1);
            atomicAdd(&od1[s1[i]], 1);
            atomicAdd(&cnt1[d1[i]], 1);
        }
    } else {
        int idx = (blockIdx.x - HBLK) * 256 + threadIdx.x;
        if (idx < 32768) {
            int mat = idx >> 13, r = idx & 8191;
            int n = r >> 6, ku = r & 63;
            int k = 2 * ku;
            const float* Wsrc = (mat == 0) ? W1r0 : (mat == 1) ? W1r1 :
                                (mat == 2) ? W2r0 : W2r1;
            float v0 = __ldg(Wsrc + k * 128 + n);
            float v1 = __ldg(Wsrc + (k + 1) * 128 + n);
            WT[mat * 16384 + n * 64 + ku]        = packbf(v0, v1);
            WT[mat * 16384 + 8192 + n * 64 + ku] = packbf(bfres(v0), bfres(v1));
        } else if (idx < 49152) {
            int r = idx - 32768;
            int n = r >> 7, ku = r & 127;
            int k = 2 * ku;
            float v0 = __ldg(Wm1 + k * 128 + n);
            float v1 = __ldg(Wm1 + (k + 1) * 128 + n);
            WT[65536 + n * 128 + ku]         = packbf(v0, v1);
            WT[65536 + 16384 + n * 128 + ku] = packbf(bfres(v0), bfres(v1));
        }
    }
}

// fused scan (verified): block sums -> last block scans -> rowptr/cursor/rs
__global__ void __launch_bounds__(256) k_scan_fused(
    const int* __restrict__ c0, const int* __restrict__ c1,
    const int* __restrict__ od0, const int* __restrict__ od1,
    int* __restrict__ bsum, int* __restrict__ pfx, int* __restrict__ syn,
    int* __restrict__ rp0, int* __restrict__ rp1,
    int* __restrict__ cur0, int* __restrict__ cur1,
    float* __restrict__ rs) {
    __shared__ int sp[256];
    __shared__ int sp2[512];
    __shared__ int islast;
    int t = threadIdx.x;
    int y = blockIdx.y;
    const int* cnt = y ? c1 : c0;
    const int* od  = y ? od1 : od0;
    int* rp  = y ? rp1 : rp0;
    int* cur = y ? cur1 : cur0;
    int i = blockIdx.x * 256 + t;
    int v = (i < NN) ? cnt[i] : 0;

    sp[t] = v;
    __syncthreads();
    for (int off = 128; off; off >>= 1) {
        if (t < off) sp[t] += sp[t + off];
        __syncthreads();
    }
    if (t == 0) {
        bsum[y * NBLK + blockIdx.x] = sp[0];
        __threadfence();
        int old = atomicAdd(&syn[0], 1);
        islast = (old == 2 * NBLK - 1);
    }
    __syncthreads();

    if (islast) {
        for (int j = t; j < 2 * NBLK; j += 256) sp2[j] = ((volatile int*)bsum)[j];
        __syncthreads();
        for (int rel = 0; rel < 2; rel++) {
            int* a = sp2 + rel * NBLK;
            int mine = (t < NBLK) ? a[t] : 0;
            sp[t] = mine;
            __syncthreads();
            for (int off = 1; off < 256; off <<= 1) {
                int u = (t >= off) ? sp[t - off] : 0;
                __syncthreads();
                sp[t] += u;
                __syncthreads();
            }
            if (t < NBLK) pfx[rel * NBLK + t] = sp[t] - mine;
            __syncthreads();
        }
        if (t == 0) {
            __threadfence();
            atomicExch(&syn[1], 1);
        }
    }
    if (t == 0) {
        while (((volatile int*)syn)[1] == 0) __nanosleep(64);
    }
    __syncthreads();

    sp[t] = v;
    __syncthreads();
    for (int off = 1; off < 256; off <<= 1) {
        int u = (t >= off) ? sp[t - off] : 0;
        __syncthreads();
        sp[t] += u;
        __syncthreads();
    }
    if (i < NN) {
        int ex = sp[t] - v + ((volatile int*)pfx)[y * NBLK + blockIdx.x];
        rp[i] = ex;
        cur[i] = ex;
        rs[(2 * y + 0) * NN + i] = rsqrtf((float)max(od[i], 1));
        rs[(2 * y + 1) * NN + i] = rsqrtf((float)max(v, 1));
    }
    if (i == NN - 1) rp[NN] = EE;
}

__global__ void k_fill(const int* __restrict__ s0, const int* __restrict__ d0,
                       const int* __restrict__ s1, const int* __restrict__ d1,
                       int* __restrict__ cur0, int* __restrict__ eidx0,
                       int* __restrict__ cur1, int* __restrict__ eidx1) {
    int i = blockIdx.x * blockDim.x + threadIdx.x;
    if (i < EE) {
        int p0 = atomicAdd(&cur0[d0[i]], 1);
        eidx0[p0] = s0[i];
        int p1 = atomicAdd(&cur1[d1[i]], 1);
        eidx1[p1] = s1[i];
    }
}

// ---------------------------------------------------------------------------
// merged gather (R8-exact, used with gridDim.y=1, slot-0 args)
__global__ void __launch_bounds__(256, 8) k_gather2(
    const float* __restrict__ xa, const int* __restrict__ ea,
    const int* __restrict__ rpa, const float* __restrict__ rsa,
    float* __restrict__ agga,
    const float* __restrict__ xb, const int* __restrict__ eb,
    const int* __restrict__ rpb, const float* __restrict__ rsb,
    float* __restrict__ aggb, int useRs) {
    const float* x  = blockIdx.y ? xb : xa;
    const int* eidx = blockIdx.y ? eb : ea;
    const int* rowptr = blockIdx.y ? rpb : rpa;
    const float* rs_src = blockIdx.y ? rsb : rsa;
    float* agg = blockIdx.y ? aggb : agga;

    int g = blockIdx.x * blockDim.x + threadIdx.x;
    int r = g >> 5, lane = g & 31;
    if (r >= NN) return;
    int beg = __ldg(rowptr + r), end = __ldg(rowptr + r + 1);
    float4 acc = make_float4(0.f, 0.f, 0.f, 0.f);
    int e = beg;
    if (useRs) {
        for (; e + 1 < end; e += 2) {
            int sa = __ldg(eidx + e), sb = __ldg(eidx + e + 1);
            float ra = __ldg(rs_src + sa), rb = __ldg(rs_src + sb);
            float4 va = __ldg((const float4*)(x + (long)sa * DD) + lane);
            float4 vb = __ldg((const float4*)(x + (long)sb * DD) + lane);
            acc.x = fmaf(va.x, ra, acc.x); acc.y = fmaf(va.y, ra, acc.y);
            acc.z = fmaf(va.z, ra, acc.z); acc.w = fmaf(va.w, ra, acc.w);
            acc.x = fmaf(vb.x, rb, acc.x); acc.y = fmaf(vb.y, rb, acc.y);
            acc.z = fmaf(vb.z, rb, acc.z); acc.w = fmaf(vb.w, rb, acc.w);
        }
        if (e < end) {
            int sa = __ldg(eidx + e);
            float ra = __ldg(rs_src + sa);
            float4 va = __ldg((const float4*)(x + (long)sa * DD) + lane);
            acc.x = fmaf(va.x, ra, acc.x); acc.y = fmaf(va.y, ra, acc.y);
            acc.z = fmaf(va.z, ra, acc.z); acc.w = fmaf(va.w, ra, acc.w);
        }
    } else {
        for (; e + 1 < end; e += 2) {
            int sa = __ldg(eidx + e), sb = __ldg(eidx + e + 1);
            float4 va = __ldg((const float4*)(x + (long)sa * DD) + lane);
            float4 vb = __ldg((const float4*)(x + (long)sb * DD) + lane);
            acc.x += va.x + vb.x; acc.y += va.y + vb.y;
            acc.z += va.z + vb.z; acc.w += va.w + vb.w;
        }
        if (e < end) {
            int sa = __ldg(eidx + e);
            float4 va = __ldg((const float4*)(x + (long)sa * DD) + lane);
            acc.x += va.x; acc.y += va.y; acc.z += va.z; acc.w += va.w;
        }
    }
    ((float4*)(agg + (long)r * DD))[lane] = acc;
}

// ---------------------------------------------------------------------------
// bf16x3 tensor-core GEMM (R8-exact, used with gridDim.y=1, slot-0 args)
#define U_AHI 0
#define U_ALO 4352
#define U_WHI 8704
#define U_WLO 17408
#define SMEM_G ((size_t)26112 * 4)

__global__ void __launch_bounds__(256, 2) k_gemm_bf16(
    const float* __restrict__ X0, const float* __restrict__ rsi0,
    const unsigned* __restrict__ Wp0, const float* __restrict__ bp0,
    float* __restrict__ out0, const float* __restrict__ rso0,
    const float* __restrict__ X1, const float* __restrict__ rsi1,
    const unsigned* __restrict__ Wp1, const float* __restrict__ bp1,
    float* __restrict__ out1, const float* __restrict__ rso1,
    int doRelu) {
    extern __shared__ unsigned smu[];
    unsigned* sAhi = smu + U_AHI;
    unsigned* sAlo = smu + U_ALO;
    unsigned* sWhi = smu + U_WHI;
    unsigned* sWlo = smu + U_WLO;

    const float* X = blockIdx.y ? X1 : X0;
    const float* rsi = blockIdx.y ? rsi1 : rsi0;
    const unsigned* Wp = blockIdx.y ? Wp1 : Wp0;
    const float* bp = blockIdx.y ? bp1 : bp0;
    float* out = blockIdx.y ? out1 : out0;
    const float* rso = blockIdx.y ? rso1 : rso0;

    int tid = threadIdx.x;
    int r0 = blockIdx.x * 64;

    for (int i = tid; i < 2048; i += 256) {
        int row = i >> 5, f4 = i & 31;
        int gr = r0 + row;
        float4 v = make_float4(0.f, 0.f, 0.f, 0.f);
        if (gr < NN) {
            v = __ldg((const float4*)(X + (long)gr * DD) + f4);
            float r = __ldg(rsi + gr);
            v.x *= r; v.y *= r; v.z *= r; v.w *= r;
        }
        ((uint2*)(sAhi + row * 68))[f4] = make_uint2(packbf(v.x, v.y), packbf(v.z, v.w));
        ((uint2*)(sAlo + row * 68))[f4] = make_uint2(
            packbf(bfres(v.x), bfres(v.y)), packbf(bfres(v.z), bfres(v.w)));
    }
    for (int i = tid; i < 4096; i += 256) {
        int n = i >> 5, q = i & 31;
        ((uint2*)(sWhi + n * 68))[q] = __ldg((const uint2*)(Wp + n * 64) + q);
        ((uint2*)(sWlo + n * 68))[q] = __ldg((const uint2*)(Wp + 8192 + n * 64) + q);
    }
    __syncthreads();

    int lane = tid & 31, w = tid >> 5;
    int mg = w >> 2, ng = w & 3;
    int tg = lane & 3, gid = lane >> 2;

    float acc[2][4][4];
#pragma unroll
    for (int mi = 0; mi < 2; mi++)
#pragma unroll
        for (int ni = 0; ni < 4; ni++)
#pragma unroll
            for (int q = 0; q < 4; q++) acc[mi][ni][q] = 0.f;

#pragma unroll
    for (int ks = 0; ks < 8; ks++) {
        unsigned Ah[2][4], Al[2][4], Bh[4][2], Bl[4][2];
#pragma unroll
        for (int mi = 0; mi < 2; mi++) {
            int base = (mg * 32 + mi * 16 + gid) * 68 + ks * 8 + tg;
            Ah[mi][0] = sAhi[base];
            Ah[mi][1] = sAhi[base + 8 * 68];
            Ah[mi][2] = sAhi[base + 4];
            Ah[mi][3] = sAhi[base + 8 * 68 + 4];
            Al[mi][0] = sAlo[base];
            Al[mi][1] = sAlo[base + 8 * 68];
            Al[mi][2] = sAlo[base + 4];
            Al[mi][3] = sAlo[base + 8 * 68 + 4];
        }
#pragma unroll
        for (int ni = 0; ni < 4; ni++) {
            int cb = (ng * 32 + ni * 8 + gid) * 68 + ks * 8 + tg;
            Bh[ni][0] = sWhi[cb];
            Bh[ni][1] = sWhi[cb + 4];
            Bl[ni][0] = sWlo[cb];
            Bl[ni][1] = sWlo[cb + 4];
        }
#pragma unroll
        for (int mi = 0; mi < 2; mi++)
#pragma unroll
            for (int ni = 0; ni < 4; ni++) {
                float* d = acc[mi][ni];
                mma_bf16(d[0], d[1], d[2], d[3],
                         Ah[mi][0], Ah[mi][1], Ah[mi][2], Ah[mi][3],
                         Bh[ni][0], Bh[ni][1]);
                mma_bf16(d[0], d[1], d[2], d[3],
                         Ah[mi][0], Ah[mi][1], Ah[mi][2], Ah[mi][3],
                         Bl[ni][0], Bl[ni][1]);
                mma_bf16(d[0], d[1], d[2], d[3],
                         Al[mi][0], Al[mi][1], Al[mi][2], Al[mi][3],
                         Bh[ni][0], Bh[ni][1]);
            }
    }

#pragma unroll
    for (int ni = 0; ni < 4; ni++) {
        int col = ng * 32 + ni * 8 + 2 * tg;
        float bb0 = __ldg(bp + col), bb1 = __ldg(bp + col + 1);
#pragma unroll
        for (int mi = 0; mi < 2; mi++) {
            int gr = r0 + mg * 32 + mi * 16 + gid;
            if (gr < NN) {
                float ro = rso ? __ldg(rso + gr) : 1.f;
                float v0 = acc[mi][ni][0] + bb0;
                float v1 = acc[mi][ni][1] + bb1;
                if (doRelu) { v0 = fmaxf(v0, 0.f); v1 = fmaxf(v1, 0.f); }
                *(float2*)(out + (long)gr * DD + col) = make_float2(v0 * ro, v1 * ro);
            }
            int gr8 = gr + 8;
            if (gr8 < NN) {
                float ro = rso ? __ldg(rso + gr8) : 1.f;
                float v2 = acc[mi][ni][2] + bb0;
                float v3 = acc[mi][ni][3] + bb1;
                if (doRelu) { v2 = fmaxf(v2, 0.f); v3 = fmaxf(v3, 0.f); }
                *(float2*)(out + (long)gr8 * DD + col) = make_float2(v2 * ro, v3 * ro);
            }
        }
    }
}

// ---------------------------------------------------------------------------
// MLP layer1 + BN stats + last-block BN finalize (R10-exact)
__global__ void __launch_bounds__(256, 2) k_mlp1_bf16(
    const float* __restrict__ XA, const float* __restrict__ XB,
    const unsigned* __restrict__ WTm1, float* __restrict__ out,
    float* __restrict__ stat, int* __restrict__ syn,
    const float* __restrict__ gamma, const float* __restrict__ beta,
    float* __restrict__ bn) {
    extern __shared__ unsigned smu[];
    unsigned* sAhi = smu + U_AHI;
    unsigned* sAlo = smu + U_ALO;
    unsigned* sWhi = smu + U_WHI;
    unsigned* sWlo = smu + U_WLO;
    int tid = threadIdx.x;
    int r0 = blockIdx.x * 64;
    int lane = tid & 31, w = tid >> 5;
    int mg = w >> 2, ng = w & 3;
    int tg = lane & 3, gid = lane >> 2;

    float acc[2][4][4];
#pragma unroll
    for (int mi = 0; mi < 2; mi++)
#pragma unroll
        for (int ni = 0; ni < 4; ni++)
#pragma unroll
            for (int q = 0; q < 4; q++) acc[mi][ni][q] = 0.f;

    for (int ph = 0; ph < 2; ph++) {
        const float* X = ph ? XB : XA;
        for (int i = tid; i < 2048; i += 256) {
            int row = i >> 5, f4 = i & 31;
            int gr = r0 + row;
            float4 v = make_float4(0.f, 0.f, 0.f, 0.f);
            if (gr < NN) v = __ldg((const float4*)(X + (long)gr * DD) + f4);
            ((uint2*)(sAhi + row * 68))[f4] = make_uint2(packbf(v.x, v.y), packbf(v.z, v.w));
            ((uint2*)(sAlo + row * 68))[f4] = make_uint2(
                packbf(bfres(v.x), bfres(v.y)), packbf(bfres(v.z), bfres(v.w)));
        }
        for (int i = tid; i < 4096; i += 256) {
            int n = i >> 5, q = i & 31;
            ((uint2*)(sWhi + n * 68))[q] =
                __ldg((const uint2*)(WTm1 + n * 128 + ph * 64) + q);
            ((uint2*)(sWlo + n * 68))[q] =
                __ldg((const uint2*)(WTm1 + 16384 + n * 128 + ph * 64) + q);
        }
        __syncthreads();

#pragma unroll
        for (int ks = 0; ks < 8; ks++) {
            unsigned Ah[2][4], Al[2][4], Bh[4][2], Bl[4][2];
#pragma unroll
            for (int mi = 0; mi < 2; mi++) {
                int base = (mg * 32 + mi * 16 + gid) * 68 + ks * 8 + tg;
                Ah[mi][0] = sAhi[base];
                Ah[mi][1] = sAhi[base + 8 * 68];
                Ah[mi][2] = sAhi[base + 4];
                Ah[mi][3] = sAhi[base + 8 * 68 + 4];
                Al[mi][0] = sAlo[base];
                Al[mi][1] = sAlo[base + 8 * 68];
                Al[mi][2] = sAlo[base + 4];
                Al[mi][3] = sAlo[base + 8 * 68 + 4];
            }
#pragma unroll
            for (int ni = 0; ni < 4; ni++) {
                int cb = (ng * 32 + ni * 8 + gid) * 68 + ks * 8 + tg;
                Bh[ni][0] = sWhi[cb];
                Bh[ni][1] = sWhi[cb + 4];
                Bl[ni][0] = sWlo[cb];
                Bl[ni][1] = sWlo[cb + 4];
            }
#pragma unroll
            for (int mi = 0; mi < 2; mi++)
#pragma unroll
                for (int ni = 0; ni < 4; ni++) {
                    float* d = acc[mi][ni];
                    mma_bf16(d[0], d[1], d[2], d[3],
                             Ah[mi][0], Ah[mi][1], Ah[mi][2], Ah[mi][3],
                             Bh[ni][0], Bh[ni][1]);
                    mma_bf16(d[0], d[1], d[2], d[3],
                             Ah[mi][0], Ah[mi][1], Ah[mi][2], Ah[mi][3],
                             Bl[ni][0], Bl[ni][1]);
                    mma_bf16(d[0], d[1], d[2], d[3],
                             Al[mi][0], Al[mi][1], Al[mi][2], Al[mi][3],
                             Bh[ni][0], Bh[ni][1]);
                }
        }
        __syncthreads();
    }

    float cs[4][2], cq[4][2];
#pragma unroll
    for (int ni = 0; ni < 4; ni++) {
        cs[ni][0] = cs[ni][1] = 0.f;
        cq[ni][0] = cq[ni][1] = 0.f;
    }
#pragma unroll
    for (int ni = 0; ni < 4; ni++) {
        int col = ng * 32 + ni * 8 + 2 * tg;
#pragma unroll
        for (int mi = 0; mi < 2; mi++) {
            int gr = r0 + mg * 32 + mi * 16 + gid;
            if (gr < NN) {
                float v0 = acc[mi][ni][0], v1 = acc[mi][ni][1];
                *(float2*)(out + (long)gr * DD + col) = make_float2(v0, v1);
                cs[ni][0] += v0; cq[ni][0] += v0 * v0;
                cs[ni][1] += v1; cq[ni][1] += v1 * v1;
            }
            int gr8 = gr + 8;
            if (gr8 < NN) {
                float v2 = acc[mi][ni][2], v3 = acc[mi][ni][3];
                *(float2*)(out + (long)gr8 * DD + col) = make_float2(v2, v3);
                cs[ni][0] += v2; cq[ni][0] += v2 * v2;
                cs[ni][1] += v3; cq[ni][1] += v3 * v3;
            }
        }
    }
    __syncthreads();
    float* ssum = (float*)smu;
    float* ssq  = (float*)smu + 128;
    if (tid < 256) ((float*)smu)[tid] = 0.f;
    __syncthreads();
#pragma unroll
    for (int ni = 0; ni < 4; ni++) {
        int col = ng * 32 + ni * 8 + 2 * tg;
        atomicAdd(&ssum[col], cs[ni][0]);
        atomicAdd(&ssum[col + 1], cs[ni][1]);
        atomicAdd(&ssq[col], cq[ni][0]);
        atomicAdd(&ssq[col + 1], cq[ni][1]);
    }
    __syncthreads();
    if (tid < 128) {
        atomicAdd(&stat[tid], ssum[tid]);
        atomicAdd(&stat[128 + tid], ssq[tid]);
    }

    __shared__ int lastblk;
    __threadfence();
    __syncthreads();
    if (tid == 0) {
        int old = atomicAdd(&syn[2], 1);
        lastblk = (old == (int)gridDim.x - 1);
    }
    __syncthreads();
    if (lastblk && tid < 128) {
        float s  = atomicAdd(&stat[tid], 0.f);
        float sq = atomicAdd(&stat[128 + tid], 0.f);
        float mu  = s * (1.f / NN);
        float var = sq * (1.f / NN) - mu * mu;
        float sc  = __ldg(gamma + tid) * rsqrtf(var + 1e-5f);
        bn[tid]       = sc;
        bn[128 + tid] = __ldg(beta + tid) - mu * sc;
    }
}

// ---------------------------------------------------------------------------
__global__ void __launch_bounds__(256) k_mlp2(
    const float* __restrict__ H, const float* __restrict__ bn,
    const float* __restrict__ Wm2, float* __restrict__ out) {
    __shared__ float sw[256];
    __shared__ float sb[256];
    int tid = threadIdx.x;
    if (tid < 256) { sw[tid] = Wm2[tid]; sb[tid] = bn[tid]; }
    __syncthreads();
    int g = blockIdx.x * blockDim.x + tid;
    int row = g >> 5, lane = g & 31;
    if (row >= NN) return;
    float4 h = ((const float4*)(H + (long)row * DD))[lane];
    float s0 = 0.f, s1 = 0.f;
    int c = lane * 4;
    float hv[4] = {h.x, h.y, h.z, h.w};
#pragma unroll
    for (int j = 0; j < 4; j++) {
        int cc = c + j;
        float v = fmaxf(hv[j] * sb[cc] + sb[128 + cc], 0.f);
        s0 += v * sw[cc * 2];
        s1 += v * sw[cc * 2 + 1];
    }
#pragma unroll
    for (int off = 16; off > 0; off >>= 1) {
        s0 += __shfl_down_sync(0xffffffffu, s0, off);
        s1 += __shfl_down_sync(0xffffffffu, s1, off);
    }
    if (lane == 0) {
        out[row * 2]     = s0;
        out[row * 2 + 1] = s1;
    }
}

// ---------------------------------------------------------------------------
extern "C" void kernel_launch(void* const* d_in, const int* in_sizes, int n_in,
                              void* d_out, int out_size) {
    const float* xA    = (const float*)d_in[0];
    const float* xB    = (const float*)d_in[1];
    const int*   s0    = (const int*)d_in[2];
    const int*   d0    = (const int*)d_in[3];
    const int*   s1    = (const int*)d_in[4];
    const int*   d1    = (const int*)d_in[5];
    const float* W1r0  = (const float*)d_in[6];
    const float* b1r0  = (const float*)d_in[7];
    const float* W1r1  = (const float*)d_in[8];
    const float* b1r1  = (const float*)d_in[9];
    const float* W2r0  = (const float*)d_in[10];
    const float* b2r0  = (const float*)d_in[11];
    const float* W2r1  = (const float*)d_in[12];
    const float* b2r1  = (const float*)d_in[13];
    const float* Wm1   = (const float*)d_in[14];
    const float* gamma = (const float*)d_in[15];
    const float* beta  = (const float*)d_in[16];
    const float* Wm2   = (const float*)d_in[17];
    float* out = (float*)d_out;

    float* S = nullptr;
    cudaGetSymbolAddress((void**)&S, g_s);
    int* I = nullptr;
    cudaGetSymbolAddress((void**)&I, g_i);

    float* AGG1B = S + OFF_AGG1B;
    float* AGG1A = S + OFF_AGG1A;
    float* AGG2B = S + OFF_AGG2B;
    float* AGG2A = S + OFF_AGG2A;
    float* HB    = S + OFF_HB;
    float* HA    = S + OFF_HA;
    float* H2A   = S + OFF_H2A;
    float* H2B   = S + OFF_H2B;
    float* HMLP  = S + OFF_HMLP;
    float* RS    = S + OFF_RS;
    float* STATS = S + OFF_STATS;
    float* BN    = S + OFF_BN;
    unsigned* WT = (unsigned*)(S + OFF_WT);

    int* eidx0 = I + IOFF_EIDX0;
    int* eidx1 = I + IOFF_EIDX1;
    int* od0   = I + IOFF_OD0;
    int* cnt0  = I + IOFF_CNT0;
    int* od1   = I + IOFF_OD1;
    int* cnt1  = I + IOFF_CNT1;
    int* rp0   = I + IOFF_RP0;
    int* rp1   = I + IOFF_RP1;
    int* cur0  = I + IOFF_CUR0;
    int* cur1  = I + IOFF_CUR1;
    int* bsum  = I + IOFF_BSUM;
    int* pfx   = I + IOFF_PFX;
    int* syn   = I + IOFF_SYNC;

    float* rs_src0 = RS + 0 * NN;
    float* rs_dst0 = RS + 1 * NN;
    float* rs_src1 = RS + 2 * NN;
    float* rs_dst1 = RS + 3 * NN;

    unsigned* W1r0T = WT + 0;
    unsigned* W1r1T = WT + 16384;
    unsigned* W2r0T = WT + 32768;
    unsigned* W2r1T = WT + 49152;
    unsigned* Wm1T  = WT + 65536;

    cudaFuncSetAttribute(k_gemm_bf16, cudaFuncAttributeMaxDynamicSharedMemorySize, (int)SMEM_G);
    cudaFuncSetAttribute(k_mlp1_bf16, cudaFuncAttributeMaxDynamicSharedMemorySize, (int)SMEM_G);

    // fork/join resources (created fresh each call; joined before return)
    cudaStream_t sB;
    cudaStreamCreateWithFlags(&sB, cudaStreamNonBlocking);
    cudaEvent_t evSetup, evHA, evHB, evDone;
    cudaEventCreateWithFlags(&evSetup, cudaEventDisableTiming);
    cudaEventCreateWithFlags(&evHA, cudaEventDisableTiming);
    cudaEventCreateWithFlags(&evHB, cudaEventDisableTiming);
    cudaEventCreateWithFlags(&evDone, cudaEventDisableTiming);

    // ---- setup chain on default stream ----
    k_zero2<<<(NN + 255) / 256, 256>>>(od0, STATS, syn);
    k_hist_wprep<<<HBLK + 192, 256>>>(s0, d0, s1, d1, od0, cnt0, od1, cnt1,
                                      W1r0, W1r1, W2r0, W2r1, Wm1, WT);
    k_scan_fused<<<dim3(NBLK, 2), 256>>>(cnt0, cnt1, od0, od1, bsum, pfx, syn,
                                         rp0, rp1, cur0, cur1, RS);
    k_fill<<<(EE + 255) / 256, 256>>>(s0, d0, s1, d1, cur0, eidx0, cur1, eidx1);
    cudaEventRecord(evSetup, 0);
    cudaStreamWaitEvent(sB, evSetup, 0);

    dim3 ggrid1((NN * 32 + 255) / 256, 1);
    dim3 tgrid1((NN + 63) / 64, 1);
    int mgrid = (NN + 63) / 64;

    // ---- stream 0 (relation 0 chain) ----
    k_gather2<<<ggrid1, 256>>>(xA, eidx0, rp0, rs_src0, AGG1B,
                               xA, eidx0, rp0, rs_src0, AGG1B, 1);
    k_gemm_bf16<<<tgrid1, 256, SMEM_G>>>(
        AGG1B, rs_dst0, W1r0T, b1r0, HB, rs_src1,
        AGG1B, rs_dst0, W1r0T, b1r0, HB, rs_src1, 1);
    cudaEventRecord(evHB, 0);

    // ---- stream B (relation 1 chain) ----
    k_gather2<<<ggrid1, 256, 0, sB>>>(xB, eidx1, rp1, rs_src1, AGG1A,
                                      xB, eidx1, rp1, rs_src1, AGG1A, 1);
    k_gemm_bf16<<<tgrid1, 256, SMEM_G, sB>>>(
        AGG1A, rs_dst1, W1r1T, b1r1, HA, rs_src0,
        AGG1A, rs_dst1, W1r1T, b1r1, HA, rs_src0, 1);
    cudaEventRecord(evHA, sB);

    // conv2 relation 0: gather from HA (needs stream B's gemm)
    cudaStreamWaitEvent(0, evHA, 0);
    k_gather2<<<ggrid1, 256>>>(HA, eidx0, rp0, nullptr, AGG2B,
                               HA, eidx0, rp0, nullptr, AGG2B, 0);
    k_gemm_bf16<<<tgrid1, 256, SMEM_G>>>(
        AGG2B, rs_dst0, W2r0T, b2r0, H2B, nullptr,
        AGG2B, rs_dst0, W2r0T, b2r0, H2B, nullptr, 0);

    // conv2 relation 1 on stream B: gather from HB (needs stream 0's conv1 gemm)
    cudaStreamWaitEvent(sB, evHB, 0);
    k_gather2<<<ggrid1, 256, 0, sB>>>(HB, eidx1, rp1, nullptr, AGG2A,
                                      HB, eidx1, rp1, nullptr, AGG2A, 0);
    k_gemm_bf16<<<tgrid1, 256, SMEM_G, sB>>>(
        AGG2A, rs_dst1, W2r1T, b2r1, H2A, nullptr,
        AGG2A, rs_dst1, W2r1T, b2r1, H2A, nullptr, 0);
    cudaEventRecord(evDone, sB);

    // join, then MLP head on stream 0
    cudaStreamWaitEvent(0, evDone, 0);
    k_mlp1_bf16<<<mgrid, 256, SMEM_G>>>(H2A, H2B, Wm1T, HMLP, STATS, syn,
                                        gamma, beta, BN);
    k_mlp2<<<(NN * 32 + 255) / 256, 256>>>(HMLP, BN, Wm2, out);
}